// round 1
// baseline (speedup 1.0000x reference)
#include <cuda_runtime.h>
#include <math.h>

#define Bc 4
#define Nc 1024
#define Hc 8
#define Dc 64
#define BSc 32
#define NBc 32
#define STOP 16
#define SCALE 0.125f   // D^-0.5 = 64^-0.5

__device__ float g_kcmp[Bc*NBc*Hc*Dc];
__device__ float g_vcmp[Bc*NBc*Hc*Dc];

__device__ __forceinline__ float siluf(float s) {
    return s / (1.f + __expf(-s));
}

// Block-mean compressed K/V: k_cmp[b,kb,h,d] = mean_j padded_k[b, kb*32+j, h, d]
__global__ void meanKV(const float* __restrict__ pk, const float* __restrict__ pv) {
    int blk = blockIdx.x;                 // b*(NB*H) + kb*H + h
    int b  = blk / (NBc*Hc);
    int kb = (blk / Hc) % NBc;
    int h  = blk % Hc;
    int d  = threadIdx.x;
    float sk = 0.f, sv = 0.f;
    int base = ((b*Nc + kb*BSc)*Hc + h)*Dc + d;
    #pragma unroll 8
    for (int j = 0; j < BSc; j++) {
        sk += pk[base + j*Hc*Dc];
        sv += pv[base + j*Hc*Dc];
    }
    int o = ((b*NBc + kb)*Hc + h)*Dc + d;
    g_kcmp[o] = sk * (1.f/BSc);
    g_vcmp[o] = sv * (1.f/BSc);
}

// One CTA per (q_block, head, batch). 256 threads = 8 warps; warp w owns query
// rows {w, w+8, w+16, w+24}. Phase A: compressed scores (lane=kb), compressed
// attention, top-k selection, gates. Phase B: for each key block in the union
// of selections, stage K (transposed, pad 33) + V in shared and accumulate the
// selected branch (lane=key for QK, lane=dim for PV).
__global__ __launch_bounds__(256) void hstu_main(
    const float* __restrict__ pq, const float* __restrict__ pk,
    const float* __restrict__ pv, const float* __restrict__ gate_w,
    const int* __restrict__ xoff, float* __restrict__ out)
{
    __shared__ float qsh[32][64];      // q rows (broadcast reads)
    __shared__ float kbuf[64*33];      // transposed [d][j], padded
    __shared__ float vbuf[32*64];      // [j][d]
    __shared__ unsigned selm[32];
    __shared__ unsigned unionm;

    int qb = blockIdx.x, h = blockIdx.y, b = blockIdx.z;
    int len = xoff[b+1] - xoff[b];
    if (qb * BSc >= len) return;       // fully-padded query block
    int t0 = xoff[b];
    int tid = threadIdx.x, lane = tid & 31, w = tid >> 5;

    // ---- stage q rows (float4, coalesced) ----
    for (int i = tid; i < 32*16; i += 256) {
        int r = i >> 4, c4 = i & 15;
        const float4* src = (const float4*)(pq + ((b*Nc + qb*BSc + r)*Hc + h)*Dc) + c4;
        ((float4*)qsh[r])[c4] = *src;
    }
    // ---- stage compressed K (transposed) / V ----
    for (int i = tid; i < NBc*Dc; i += 256) {
        int kb = i >> 6, d = i & 63;
        int g = ((b*NBc + kb)*Hc + h)*Dc + d;
        kbuf[d*33 + kb] = g_kcmp[g];
        vbuf[kb*64 + d] = g_vcmp[g];
    }
    if (tid == 0) unionm = 0;
    __syncthreads();

    float accC0[4], accC1[4], accS0[4], accS1[4], gcv[4], gsv[4];
    unsigned mysel[4];

    // ================= Phase A =================
    for (int qi = 0; qi < 4; qi++) {
        int r = w + qi*8;
        int n = qb*BSc + r;
        accC0[qi]=accC1[qi]=accS0[qi]=accS1[qi]=0.f;
        mysel[qi]=0; gcv[qi]=gsv[qi]=0.f;
        if (n >= len) { if (lane == 0) selm[r] = 0u; continue; }

        // compressed scores: lane = kb
        float s = 0.f;
        #pragma unroll
        for (int d = 0; d < 64; d++) s += qsh[r][d] * kbuf[d*33 + lane];
        s *= SCALE;
        bool causal = (lane <= qb);
        float p = causal ? siluf(s) : 0.f;

        // compressed attention: lane = dim (d0=lane, d1=lane+32)
        for (int kb = 0; kb <= qb; kb++) {
            float pb = __shfl_sync(0xffffffffu, p, kb);
            accC0[qi] += pb * vbuf[kb*64 + lane];
            accC1[qi] += pb * vbuf[kb*64 + 32 + lane];
        }

        // top-k selection (set semantics of jax.lax.top_k, ties -> lower index)
        unsigned sel;
        if (qb < STOP) {
            sel = (1u << (qb + 1)) - 1u;   // all causal blocks (qb+1 <= 16)
        } else {
            float val = causal ? s : -__int_as_float(0x7f800000);
            sel = 0u;
            for (int it = 0; it < STOP; it++) {
                float bv = val; int bi = lane;
                #pragma unroll
                for (int off = 16; off > 0; off >>= 1) {
                    float ov = __shfl_xor_sync(0xffffffffu, bv, off);
                    int   oi = __shfl_xor_sync(0xffffffffu, bi, off);
                    if (ov > bv || (ov == bv && oi < bi)) { bv = ov; bi = oi; }
                }
                sel |= (1u << bi);
                if (lane == bi) val = -__int_as_float(0x7f800000);
            }
        }
        mysel[qi] = sel;
        if (lane == 0) selm[r] = sel;

        // gates: sigmoid(q . gate_w[h,:,g]) for g=0 (cmp), g=1 (slc)
        float q0 = qsh[r][lane], q1 = qsh[r][lane + 32];
        const float* gw = gate_w + h*Dc*3;
        float pg0 = q0*gw[lane*3 + 0] + q1*gw[(lane+32)*3 + 0];
        float pg1 = q0*gw[lane*3 + 1] + q1*gw[(lane+32)*3 + 1];
        #pragma unroll
        for (int off = 16; off > 0; off >>= 1) {
            pg0 += __shfl_xor_sync(0xffffffffu, pg0, off);
            pg1 += __shfl_xor_sync(0xffffffffu, pg1, off);
        }
        gcv[qi] = 1.f / (1.f + __expf(-pg0));
        gsv[qi] = 1.f / (1.f + __expf(-pg1));
    }
    __syncthreads();  // phase-A reads of kbuf/vbuf done; selm written
    if (lane == 0)
        atomicOr(&unionm, selm[w] | selm[w+8] | selm[w+16] | selm[w+24]);
    __syncthreads();
    unsigned um = unionm;

    // ================= Phase B: selected branch =================
    for (int kb = 0; kb <= qb; kb++) {
        if (!((um >> kb) & 1u)) continue;
        // stage K tile transposed + V tile (coalesced gmem, conflict-free STS)
        for (int i = tid; i < BSc*Dc; i += 256) {
            int j = i >> 6, d = i & 63;
            int g = ((b*Nc + kb*BSc + j)*Hc + h)*Dc + d;
            kbuf[d*33 + j] = pk[g];
            vbuf[j*64 + d] = pv[g];
        }
        __syncthreads();

        for (int qi = 0; qi < 4; qi++) {
            if (!((mysel[qi] >> kb) & 1u)) continue;
            int r = w + qi*8;
            float s = 0.f;
            #pragma unroll
            for (int d = 0; d < 64; d++) s += qsh[r][d] * kbuf[d*33 + lane];
            s *= SCALE;
            int jmax = (kb == qb) ? r : 31;     // token-level causal within diag block
            float p = (lane <= jmax) ? siluf(s) : 0.f;
            for (int j = 0; j <= jmax; j++) {
                float pb = __shfl_sync(0xffffffffu, p, j);
                accS0[qi] += pb * vbuf[j*64 + lane];
                accS1[qi] += pb * vbuf[j*64 + 32 + lane];
            }
        }
        __syncthreads();  // protect next tile load
    }

    // ================= Output (jagged: t = x_offsets[b] + n) =================
    for (int qi = 0; qi < 4; qi++) {
        int r = w + qi*8, n = qb*BSc + r;
        if (n >= len) continue;
        int o = ((t0 + n)*Hc + h)*Dc;
        out[o + lane]      = accC0[qi]*gcv[qi] + accS0[qi]*gsv[qi];
        out[o + lane + 32] = accC1[qi]*gcv[qi] + accS1[qi]*gsv[qi];
    }
}

extern "C" void kernel_launch(void* const* d_in, const int* in_sizes, int n_in,
                              void* d_out, int out_size) {
    // metadata order: 0 jagged_q, 1 jagged_k, 2 jagged_v, 3 jagged_u,
    //                 4 padded_q, 5 padded_k, 6 padded_v, 7 x_offsets,
    //                 8 gate_w, 9 padding_mask, 10 gather_idx
    const float* pq   = (const float*)d_in[4];
    const float* pk   = (const float*)d_in[5];
    const float* pv   = (const float*)d_in[6];
    const int*   xoff = (const int*)d_in[7];
    const float* gw   = (const float*)d_in[8];
    float* out = (float*)d_out;

    meanKV<<<Bc*NBc*Hc, 64>>>(pk, pv);
    dim3 grid(NBc, Hc, Bc);
    hstu_main<<<grid, 256>>>(pq, pk, pv, gw, xoff, out);
}

// round 2
// speedup vs baseline: 2.2573x; 2.2573x over previous
#include <cuda_runtime.h>
#include <math.h>

#define Bc 4
#define Nc 1024
#define Hc 8
#define Dc 64
#define BSc 32
#define NBc 32
#define STOP 16
#define SCALE 0.125f      // D^-0.5
#define KPAD 132          // 128 floats + 16B pad per d4 row (33*16B -> bank-conflict-free)

__device__ float g_kcmp[Bc*NBc*Hc*Dc];
__device__ float g_vcmp[Bc*NBc*Hc*Dc];

__device__ __forceinline__ float siluf(float s) {
    return s / (1.f + __expf(-s));
}

// Block-mean compressed K/V
__global__ void meanKV(const float* __restrict__ pk, const float* __restrict__ pv) {
    int blk = blockIdx.x;
    int b  = blk / (NBc*Hc);
    int kb = (blk / Hc) % NBc;
    int h  = blk % Hc;
    int d  = threadIdx.x;
    float sk = 0.f, sv = 0.f;
    int base = ((b*Nc + kb*BSc)*Hc + h)*Dc + d;
    #pragma unroll 8
    for (int j = 0; j < BSc; j++) {
        sk += pk[base + j*Hc*Dc];
        sv += pv[base + j*Hc*Dc];
    }
    int o = ((b*NBc + kb)*Hc + h)*Dc + d;
    g_kcmp[o] = sk * (1.f/BSc);
    g_vcmp[o] = sv * (1.f/BSc);
}

// One CTA per (q_block, head, batch); 8 warps; warp w owns query rows
// {w, w+8, w+16, w+24}. Lane = key index for QK scores, lane = dim-pair
// (2*lane, 2*lane+1) for PV accumulation.
__global__ __launch_bounds__(256) void hstu_main(
    const float* __restrict__ pq, const float* __restrict__ pk,
    const float* __restrict__ pv, const float* __restrict__ gate_w,
    const int* __restrict__ xoff, float* __restrict__ out)
{
    __shared__ __align__(16) float qsh[32*64];      // q rows
    __shared__ __align__(16) float kb4[16*KPAD];    // K: [d4][key][4] padded
    __shared__ __align__(16) float vbuf[32*64];     // V: [key][d]
    __shared__ unsigned selm[32];
    __shared__ unsigned unionm;

    int qb = (NBc - 1) - blockIdx.x;   // heavy blocks first
    int h = blockIdx.y, b = blockIdx.z;
    int len = xoff[b+1] - xoff[b];
    if (qb * BSc >= len) return;
    int t0 = xoff[b];
    int tid = threadIdx.x, lane = tid & 31, w = tid >> 5;
    const float4* qsh4 = (const float4*)qsh;

    // ---- stage q (float4 coalesced) ----
    for (int i = tid; i < 32*16; i += 256) {
        int r = i >> 4, c4 = i & 15;
        ((float4*)qsh)[r*16 + c4] =
            ((const float4*)(pq + ((b*Nc + qb*BSc + r)*Hc + h)*Dc))[c4];
    }
    // ---- stage compressed K (d4-major) / V ----
    for (int i = tid; i < 512; i += 256) {
        int row = i >> 4, c4 = i & 15;
        const float4* src = (const float4*)(g_kcmp + ((b*NBc + row)*Hc + h)*Dc);
        *((float4*)(kb4 + c4*KPAD) + row) = src[c4];
        const float4* srcv = (const float4*)(g_vcmp + ((b*NBc + row)*Hc + h)*Dc);
        ((float4*)vbuf)[row*16 + c4] = srcv[c4];
    }
    if (tid == 0) unionm = 0;
    __syncthreads();

    float accC0[4], accC1[4], accS0[4], accS1[4], gcv[4], gsv[4], p[4];
    unsigned mysel[4];

    // ================= Phase A: compressed scores / attention / top-k / gates ===
    {
        float s[4] = {0.f, 0.f, 0.f, 0.f};
        #pragma unroll 4
        for (int d4 = 0; d4 < 16; d4++) {
            float4 kv = *((const float4*)(kb4 + d4*KPAD) + lane);
            #pragma unroll
            for (int qi = 0; qi < 4; qi++) {
                float4 q = qsh4[(w + qi*8)*16 + d4];
                s[qi] += q.x*kv.x + q.y*kv.y + q.z*kv.z + q.w*kv.w;
            }
        }
        bool causal = (lane <= qb);
        #pragma unroll
        for (int qi = 0; qi < 4; qi++) {
            int r = w + qi*8;
            int n = qb*BSc + r;
            accC0[qi]=accC1[qi]=accS0[qi]=accS1[qi]=0.f;
            float sc = s[qi] * SCALE;
            p[qi] = causal ? siluf(sc) : 0.f;
            // ---- top-k selection ----
            unsigned sel;
            if (n >= len) {
                sel = 0u; p[qi] = 0.f;
            } else if (qb < STOP) {
                sel = (1u << (qb + 1)) - 1u;
            } else {
                float val = causal ? sc : -__int_as_float(0x7f800000);
                sel = 0u;
                for (int it = 0; it < STOP; it++) {
                    float bv = val; int bi = lane;
                    #pragma unroll
                    for (int off = 16; off > 0; off >>= 1) {
                        float ov = __shfl_xor_sync(0xffffffffu, bv, off);
                        int   oi = __shfl_xor_sync(0xffffffffu, bi, off);
                        if (ov > bv || (ov == bv && oi < bi)) { bv = ov; bi = oi; }
                    }
                    sel |= (1u << bi);
                    if (lane == bi) val = -__int_as_float(0x7f800000);
                }
            }
            mysel[qi] = sel;
            if (lane == 0) selm[r] = sel;
            // ---- gates (d0=2*lane, d1=2*lane+1) ----
            float q0 = qsh[r*64 + 2*lane], q1 = qsh[r*64 + 2*lane + 1];
            const float* gw = gate_w + h*Dc*3;
            float pg0 = q0*gw[(2*lane)*3 + 0] + q1*gw[(2*lane+1)*3 + 0];
            float pg1 = q0*gw[(2*lane)*3 + 1] + q1*gw[(2*lane+1)*3 + 1];
            #pragma unroll
            for (int off = 16; off > 0; off >>= 1) {
                pg0 += __shfl_xor_sync(0xffffffffu, pg0, off);
                pg1 += __shfl_xor_sync(0xffffffffu, pg1, off);
            }
            gcv[qi] = 1.f / (1.f + __expf(-pg0));
            gsv[qi] = 1.f / (1.f + __expf(-pg1));
        }
        // ---- compressed attention PV (keys = blocks 0..qb) ----
        #pragma unroll 4
        for (int j = 0; j <= qb; j++) {
            float2 v = *((const float2*)(vbuf + j*64) + lane);
            #pragma unroll
            for (int qi = 0; qi < 4; qi++) {
                float pb = __shfl_sync(0xffffffffu, p[qi], j);
                accC0[qi] += pb * v.x;
                accC1[qi] += pb * v.y;
            }
        }
    }
    __syncthreads();
    if (lane == 0)
        atomicOr(&unionm, selm[w] | selm[w+8] | selm[w+16] | selm[w+24]);
    unsigned wsel = mysel[0] | mysel[1] | mysel[2] | mysel[3];
    __syncthreads();
    unsigned um = unionm;

    // ================= Phase B: selected branch over union of blocks =========
    for (int kb = 0; kb <= qb; kb++) {
        if (!((um >> kb) & 1u)) continue;
        // stage K (d4-major) + V tiles
        for (int i = tid; i < 512; i += 256) {
            int j = i >> 4, c4 = i & 15;
            const float4* srck = (const float4*)(pk + ((b*Nc + kb*BSc + j)*Hc + h)*Dc);
            *((float4*)(kb4 + c4*KPAD) + j) = srck[c4];
            const float4* srcv = (const float4*)(pv + ((b*Nc + kb*BSc + j)*Hc + h)*Dc);
            ((float4*)vbuf)[j*16 + c4] = srcv[c4];
        }
        __syncthreads();

        if ((wsel >> kb) & 1u) {
            float s[4] = {0.f, 0.f, 0.f, 0.f};
            #pragma unroll 4
            for (int d4 = 0; d4 < 16; d4++) {
                float4 kv = *((const float4*)(kb4 + d4*KPAD) + lane);
                #pragma unroll
                for (int qi = 0; qi < 4; qi++) {
                    float4 q = qsh4[(w + qi*8)*16 + d4];
                    s[qi] += q.x*kv.x + q.y*kv.y + q.z*kv.z + q.w*kv.w;
                }
            }
            #pragma unroll
            for (int qi = 0; qi < 4; qi++) {
                int r = w + qi*8;
                int jmax = (kb == qb) ? r : 31;
                bool use = ((mysel[qi] >> kb) & 1u) && (lane <= jmax);
                p[qi] = use ? siluf(s[qi] * SCALE) : 0.f;
            }
            #pragma unroll 4
            for (int j = 0; j < 32; j++) {
                float2 v = *((const float2*)(vbuf + j*64) + lane);
                #pragma unroll
                for (int qi = 0; qi < 4; qi++) {
                    float pb = __shfl_sync(0xffffffffu, p[qi], j);
                    accS0[qi] += pb * v.x;
                    accS1[qi] += pb * v.y;
                }
            }
        }
        __syncthreads();
    }

    // ================= Output (jagged) =================
    #pragma unroll
    for (int qi = 0; qi < 4; qi++) {
        int r = w + qi*8, n = qb*BSc + r;
        if (n >= len) continue;
        int o = ((t0 + n)*Hc + h)*Dc;
        float2 o2;
        o2.x = accC0[qi]*gcv[qi] + accS0[qi]*gsv[qi];
        o2.y = accC1[qi]*gcv[qi] + accS1[qi]*gsv[qi];
        *((float2*)(out + o) + lane) = o2;
    }
}

extern "C" void kernel_launch(void* const* d_in, const int* in_sizes, int n_in,
                              void* d_out, int out_size) {
    const float* pq   = (const float*)d_in[4];
    const float* pk   = (const float*)d_in[5];
    const float* pv   = (const float*)d_in[6];
    const int*   xoff = (const int*)d_in[7];
    const float* gw   = (const float*)d_in[8];
    float* out = (float*)d_out;

    meanKV<<<Bc*NBc*Hc, 64>>>(pk, pv);
    dim3 grid(NBc, Hc, Bc);
    hstu_main<<<grid, 256>>>(pq, pk, pv, gw, xoff, out);
}

// round 3
// speedup vs baseline: 2.8666x; 1.2699x over previous
#include <cuda_runtime.h>
#include <math.h>

#define Bc 4
#define Nc 1024
#define Hc 8
#define Dc 64
#define BSc 32
#define NBc 32
#define STOP 16
#define SCALE 0.125f

__device__ float g_kcmp[Bc*NBc*Hc*Dc];
__device__ float g_vcmp[Bc*NBc*Hc*Dc];

__device__ __forceinline__ float siluf(float s) {
    return s / (1.f + __expf(-s));
}
__device__ __forceinline__ float f4c(const float4& v, int jj) {
    switch (jj) { case 0: return v.x; case 1: return v.y; case 2: return v.z; default: return v.w; }
}

__global__ void meanKV(const float* __restrict__ pk, const float* __restrict__ pv) {
    int blk = blockIdx.x;
    int b  = blk / (NBc*Hc);
    int kb = (blk / Hc) % NBc;
    int h  = blk % Hc;
    int d  = threadIdx.x;
    float sk = 0.f, sv = 0.f;
    int base = ((b*Nc + kb*BSc)*Hc + h)*Dc + d;
    #pragma unroll 8
    for (int j = 0; j < BSc; j++) {
        sk += pk[base + j*Hc*Dc];
        sv += pv[base + j*Hc*Dc];
    }
    int o = ((b*NBc + kb)*Hc + h)*Dc + d;
    g_kcmp[o] = sk * (1.f/BSc);
    g_vcmp[o] = sv * (1.f/BSc);
}

// CTA = (q_block, head, batch); 8 warps; warp w owns query rows {w,w+8,w+16,w+24}.
// QK: lane = key (2 keys in paired tiles). PV: lane = dim-pair, p via shared.
__global__ __launch_bounds__(256) void hstu_main(
    const float* __restrict__ pq, const float* __restrict__ pk,
    const float* __restrict__ pvv, const float* __restrict__ gate_w,
    const int* __restrict__ xoff, float* __restrict__ out)
{
    __shared__ __align__(16) float4 qsh4[32*16];   // 8KB  q rows
    __shared__ __align__(16) float4 kb4[16*64];    // 16KB K swizzled: [d4][key^d4], 64 keys
    __shared__ __align__(16) float4 vb4[64*16];    // 16KB V: [key][d4], 64 keys
    __shared__ __align__(16) float  p_sh[32*64];   // 8KB  p[row][key 0..63]
    __shared__ int list[34];
    __shared__ int lcnt;
    __shared__ unsigned unionm;

    int qb = (NBc - 1) - blockIdx.x;   // heavy first
    int h = blockIdx.y, b = blockIdx.z;
    int len = xoff[b+1] - xoff[b];
    if (qb * BSc >= len) return;
    int nvalid = len - qb*BSc; if (nvalid > BSc) nvalid = BSc;
    int t0 = xoff[b];
    int tid = threadIdx.x, lane = tid & 31, w = tid >> 5;
    const float2* vb2 = (const float2*)vb4;

    // ---- stage q + compressed K/V (swizzled) ----
    for (int i = tid; i < 512; i += 256) {
        int r = i >> 4, c4 = i & 15;
        qsh4[r*16 + c4] = ((const float4*)(pq + ((b*Nc + qb*BSc + r)*Hc + h)*Dc))[c4];
        kb4[c4*64 + (r ^ c4)] = ((const float4*)(g_kcmp + ((b*NBc + r)*Hc + h)*Dc))[c4];
        vb4[r*16 + c4]        = ((const float4*)(g_vcmp + ((b*NBc + r)*Hc + h)*Dc))[c4];
    }
    if (tid == 0) unionm = 0;
    __syncthreads();

    float accC0[4], accC1[4], accS0[4], accS1[4], gcv[4], gsv[4];
    unsigned mysel[4];

    // ================= Phase A =================
    {
        float s[4] = {0.f,0.f,0.f,0.f};
        #pragma unroll
        for (int d4 = 0; d4 < 16; d4++) {
            float4 k0 = kb4[d4*64 + (lane ^ d4)];
            #pragma unroll
            for (int qi = 0; qi < 4; qi++) {
                float4 q = qsh4[(w + qi*8)*16 + d4];
                s[qi] += q.x*k0.x + q.y*k0.y + q.z*k0.z + q.w*k0.w;
            }
        }
        bool causal = (lane <= qb);
        #pragma unroll
        for (int qi = 0; qi < 4; qi++) {
            int r = w + qi*8;
            accC0[qi]=accC1[qi]=accS0[qi]=accS1[qi]=0.f;
            float sc = s[qi] * SCALE;
            bool rowok = (r < nvalid);
            float pval = (causal && rowok) ? siluf(sc) : 0.f;
            p_sh[r*64 + lane] = pval;

            // ---- exact top-16 mask ----
            unsigned sel;
            if (!rowok) {
                sel = 0u;
            } else if (qb < STOP) {
                sel = (1u << (qb + 1)) - 1u;
            } else {
                unsigned ub = __float_as_uint(sc);
                unsigned u = ((int)ub < 0) ? ~ub : (ub | 0x80000000u);
                if (!causal) u = 0u;
                unsigned T = 0u;
                #pragma unroll
                for (int bit = 31; bit >= 0; --bit) {
                    unsigned cand = T | (1u << bit);
                    unsigned bal = __ballot_sync(0xffffffffu, u >= cand);
                    if (__popc(bal) >= STOP) T = cand;
                }
                unsigned gt = __ballot_sync(0xffffffffu, u > T);
                unsigned eq = __ballot_sync(0xffffffffu, u == T);
                int need = STOP - __popc(gt);
                bool take = ((eq >> lane) & 1u) &&
                            (__popc(eq & ((1u << lane) - 1u)) < need);
                unsigned eqt = __ballot_sync(0xffffffffu, take);
                sel = gt | eqt;
            }
            mysel[qi] = sel;

            // ---- gates (dims 2*lane, 2*lane+1) ----
            const float* qs = (const float*)qsh4;
            float q0 = qs[r*64 + 2*lane], q1 = qs[r*64 + 2*lane + 1];
            const float* gw = gate_w + h*Dc*3;
            float pg0 = q0*gw[(2*lane)*3 + 0] + q1*gw[(2*lane+1)*3 + 0];
            float pg1 = q0*gw[(2*lane)*3 + 1] + q1*gw[(2*lane+1)*3 + 1];
            #pragma unroll
            for (int off = 16; off > 0; off >>= 1) {
                pg0 += __shfl_xor_sync(0xffffffffu, pg0, off);
                pg1 += __shfl_xor_sync(0xffffffffu, pg1, off);
            }
            gcv[qi] = 1.f / (1.f + __expf(-pg0));
            gsv[qi] = 1.f / (1.f + __expf(-pg1));
        }
        __syncwarp();
        unsigned wsel0 = mysel[0] | mysel[1] | mysel[2] | mysel[3];
        if (lane == 0) atomicOr(&unionm, wsel0);

        // ---- compressed PV (keys 0..qb) ----
        int j4hi = qb >> 2;
        for (int j4 = 0; j4 <= j4hi; j4++) {
            float4 pb[4];
            #pragma unroll
            for (int qi = 0; qi < 4; qi++)
                pb[qi] = *(const float4*)&p_sh[(w + qi*8)*64 + j4*4];
            #pragma unroll
            for (int jj = 0; jj < 4; jj++) {
                float2 v = vb2[(j4*4 + jj)*32 + lane];
                #pragma unroll
                for (int qi = 0; qi < 4; qi++) {
                    float pj = f4c(pb[qi], jj);
                    accC0[qi] += pj * v.x;
                    accC1[qi] += pj * v.y;
                }
            }
        }
    }
    unsigned wsel = mysel[0] | mysel[1] | mysel[2] | mysel[3];
    __syncthreads();
    unsigned um = unionm;
    if (tid == 0) {
        int c = 0;
        for (int kb = 0; kb <= qb; kb++)
            if ((um >> kb) & 1u) list[c++] = kb;
        lcnt = c;
        list[c] = list[c > 0 ? c - 1 : 0];
    }
    __syncthreads();
    int cnt = lcnt;

    // ================= Phase B: paired selected tiles =================
    for (int it = 0; it < cnt; it += 2) {
        int kb0 = list[it];
        int kb1 = list[it + 1];
        bool valid1 = (it + 1 < cnt);
        for (int i = tid; i < 512; i += 256) {
            int row = i >> 4, c4 = i & 15;
            int g0 = ((b*Nc + kb0*BSc + row)*Hc + h)*Dc;
            int g1 = ((b*Nc + kb1*BSc + row)*Hc + h)*Dc;
            kb4[c4*64 + (row ^ c4)]        = ((const float4*)(pk + g0))[c4];
            kb4[c4*64 + ((row + 32) ^ c4)] = ((const float4*)(pk + g1))[c4];
            vb4[row*16 + c4]        = ((const float4*)(pvv + g0))[c4];
            vb4[(row + 32)*16 + c4] = ((const float4*)(pvv + g1))[c4];
        }
        __syncthreads();

        bool need0 = (wsel >> kb0) & 1u;
        bool need1 = valid1 && ((wsel >> kb1) & 1u);
        if (need0 | need1) {
            float s0[4] = {0.f,0.f,0.f,0.f}, s1[4] = {0.f,0.f,0.f,0.f};
            #pragma unroll
            for (int d4 = 0; d4 < 16; d4++) {
                float4 k0 = kb4[d4*64 + (lane ^ d4)];
                float4 k1 = kb4[d4*64 + ((lane + 32) ^ d4)];
                #pragma unroll
                for (int qi = 0; qi < 4; qi++) {
                    float4 q = qsh4[(w + qi*8)*16 + d4];
                    s0[qi] += q.x*k0.x + q.y*k0.y + q.z*k0.z + q.w*k0.w;
                    s1[qi] += q.x*k1.x + q.y*k1.y + q.z*k1.z + q.w*k1.w;
                }
            }
            #pragma unroll
            for (int qi = 0; qi < 4; qi++) {
                int r = w + qi*8;
                int jmax0 = (kb0 == qb) ? r : 31;
                int jmax1 = (kb1 == qb) ? r : 31;
                bool u0 = ((mysel[qi] >> kb0) & 1u) && (lane <= jmax0);
                bool u1 = valid1 && ((mysel[qi] >> kb1) & 1u) && (lane <= jmax1);
                p_sh[r*64 + lane]      = u0 ? siluf(s0[qi]*SCALE) : 0.f;
                p_sh[r*64 + 32 + lane] = u1 ? siluf(s1[qi]*SCALE) : 0.f;
            }
            __syncwarp();
            if (need0) {
                #pragma unroll
                for (int j4 = 0; j4 < 8; j4++) {
                    float4 pb[4];
                    #pragma unroll
                    for (int qi = 0; qi < 4; qi++)
                        pb[qi] = *(const float4*)&p_sh[(w + qi*8)*64 + j4*4];
                    #pragma unroll
                    for (int jj = 0; jj < 4; jj++) {
                        float2 v = vb2[(j4*4 + jj)*32 + lane];
                        #pragma unroll
                        for (int qi = 0; qi < 4; qi++) {
                            float pj = f4c(pb[qi], jj);
                            accS0[qi] += pj * v.x;
                            accS1[qi] += pj * v.y;
                        }
                    }
                }
            }
            if (need1) {
                #pragma unroll
                for (int j4 = 8; j4 < 16; j4++) {
                    float4 pb[4];
                    #pragma unroll
                    for (int qi = 0; qi < 4; qi++)
                        pb[qi] = *(const float4*)&p_sh[(w + qi*8)*64 + j4*4];
                    #pragma unroll
                    for (int jj = 0; jj < 4; jj++) {
                        float2 v = vb2[(j4*4 + jj)*32 + lane];
                        #pragma unroll
                        for (int qi = 0; qi < 4; qi++) {
                            float pj = f4c(pb[qi], jj);
                            accS0[qi] += pj * v.x;
                            accS1[qi] += pj * v.y;
                        }
                    }
                }
            }
        }
        __syncthreads();
    }

    // ================= Output =================
    #pragma unroll
    for (int qi = 0; qi < 4; qi++) {
        int r = w + qi*8;
        if (r >= nvalid) continue;
        int n = qb*BSc + r;
        int o = ((t0 + n)*Hc + h)*Dc;
        float2 o2;
        o2.x = accC0[qi]*gcv[qi] + accS0[qi]*gsv[qi];
        o2.y = accC1[qi]*gcv[qi] + accS1[qi]*gsv[qi];
        *((float2*)(out + o) + lane) = o2;
    }
}

extern "C" void kernel_launch(void* const* d_in, const int* in_sizes, int n_in,
                              void* d_out, int out_size) {
    const float* pq   = (const float*)d_in[4];
    const float* pk   = (const float*)d_in[5];
    const float* pv   = (const float*)d_in[6];
    const int*   xoff = (const int*)d_in[7];
    const float* gw   = (const float*)d_in[8];
    float* out = (float*)d_out;

    meanKV<<<Bc*NBc*Hc, 64>>>(pk, pv);
    dim3 grid(NBc, Hc, Bc);
    hstu_main<<<grid, 256>>>(pq, pk, pv, gw, xoff, out);
}

// round 4
// speedup vs baseline: 3.0867x; 1.0768x over previous
#include <cuda_runtime.h>
#include <math.h>

#define Bc 4
#define Nc 1024
#define Hc 8
#define Dc 64
#define BSc 32
#define NBc 32
#define STOP 16
#define SCALE 0.125f

typedef unsigned long long u64;

__device__ float g_kcmp[Bc*NBc*Hc*Dc];
__device__ float g_vcmp[Bc*NBc*Hc*Dc];

__device__ __forceinline__ float siluf(float s) {
    return s / (1.f + __expf(-s));
}
// packed fp32x2 FMA (bit-identical to two FFMAs, one issue slot)
__device__ __forceinline__ u64 ffma2(u64 a, u64 b, u64 c) {
    u64 d;
    asm("fma.rn.f32x2 %0, %1, %2, %3;" : "=l"(d) : "l"(a), "l"(b), "l"(c));
    return d;
}
__device__ __forceinline__ u64 dup2(float x) {
    u64 r;
    asm("mov.b64 %0, {%1, %1};" : "=l"(r) : "f"(x));
    return r;
}
__device__ __forceinline__ float2 u2f2(u64 u) {
    float2 f;
    asm("mov.b64 {%0, %1}, %2;" : "=f"(f.x), "=f"(f.y) : "l"(u));
    return f;
}
__device__ __forceinline__ float f4c(const float4& v, int jj) {
    switch (jj) { case 0: return v.x; case 1: return v.y; case 2: return v.z; default: return v.w; }
}

__global__ void meanKV(const float* __restrict__ pk, const float* __restrict__ pv) {
    int blk = blockIdx.x;
    int b  = blk / (NBc*Hc);
    int kb = (blk / Hc) % NBc;
    int h  = blk % Hc;
    int d  = threadIdx.x;
    float sk = 0.f, sv = 0.f;
    int base = ((b*Nc + kb*BSc)*Hc + h)*Dc + d;
    #pragma unroll 8
    for (int j = 0; j < BSc; j++) {
        sk += pk[base + j*Hc*Dc];
        sv += pv[base + j*Hc*Dc];
    }
    int o = ((b*NBc + kb)*Hc + h)*Dc + d;
    g_kcmp[o] = sk * (1.f/BSc);
    g_vcmp[o] = sv * (1.f/BSc);
}

// CTA = (q_block, head, batch); 8 warps; warp w owns query rows {w,w+8,w+16,w+24}.
__global__ __launch_bounds__(256) void hstu_main(
    const float* __restrict__ pq, const float* __restrict__ pk,
    const float* __restrict__ pvv, const float* __restrict__ gate_w,
    const int* __restrict__ xoff, float* __restrict__ out)
{
    __shared__ __align__(16) float4 qsh4[32*16];   // 8KB
    __shared__ __align__(16) float4 kb4[16*64];    // 16KB K swizzled [d4][key^d4]
    __shared__ __align__(16) float4 vb4[64*16];    // 16KB V [key][d4]
    __shared__ __align__(16) float  p_sh[32*64];   // 8KB
    __shared__ int list[34];
    __shared__ int lcnt;
    __shared__ unsigned unionm;

    int qb = (NBc - 1) - blockIdx.x;
    int h = blockIdx.y, b = blockIdx.z;
    int len = xoff[b+1] - xoff[b];
    if (qb * BSc >= len) return;
    int nvalid = len - qb*BSc; if (nvalid > BSc) nvalid = BSc;
    int t0 = xoff[b];
    int tid = threadIdx.x, lane = tid & 31, w = tid >> 5;

    const ulonglong2* qshU = (const ulonglong2*)qsh4;
    const ulonglong2* kbU  = (const ulonglong2*)kb4;
    const u64*        vbU  = (const u64*)vb4;     // vbU[key*32 + lane] = dims (2l,2l+1)

    // ---- stage q + compressed K/V ----
    for (int i = tid; i < 512; i += 256) {
        int r = i >> 4, c4 = i & 15;
        qsh4[r*16 + c4] = ((const float4*)(pq + ((b*Nc + qb*BSc + r)*Hc + h)*Dc))[c4];
        kb4[c4*64 + (r ^ c4)] = ((const float4*)(g_kcmp + ((b*NBc + r)*Hc + h)*Dc))[c4];
        vb4[r*16 + c4]        = ((const float4*)(g_vcmp + ((b*NBc + r)*Hc + h)*Dc))[c4];
    }
    if (tid == 0) unionm = 0;
    __syncthreads();

    u64 accC[4], accS[4];
    unsigned mysel[4];

    // ================= Phase A =================
    {
        u64 sa[4] = {0,0,0,0}, sb[4] = {0,0,0,0};
        #pragma unroll
        for (int d4 = 0; d4 < 16; d4++) {
            ulonglong2 k0 = kbU[d4*64 + (lane ^ d4)];
            #pragma unroll
            for (int qi = 0; qi < 4; qi++) {
                ulonglong2 q = qshU[(w + qi*8)*16 + d4];
                sa[qi] = ffma2(q.x, k0.x, sa[qi]);
                sb[qi] = ffma2(q.y, k0.y, sb[qi]);
            }
        }
        bool causal = (lane <= qb);
        #pragma unroll
        for (int qi = 0; qi < 4; qi++) {
            int r = w + qi*8;
            accC[qi] = 0; accS[qi] = 0;
            float2 fa = u2f2(sa[qi]), fb = u2f2(sb[qi]);
            float sc = ((fa.x + fa.y) + (fb.x + fb.y)) * SCALE;
            bool rowok = (r < nvalid);
            p_sh[r*64 + lane] = (causal && rowok) ? siluf(sc) : 0.f;

            unsigned sel;
            if (!rowok) {
                sel = 0u;
            } else if (qb < STOP) {
                sel = (1u << (qb + 1)) - 1u;
            } else {
                unsigned ub = __float_as_uint(sc);
                unsigned u = ((int)ub < 0) ? ~ub : (ub | 0x80000000u);
                if (!causal) u = 0u;
                unsigned T = 0u;
                #pragma unroll
                for (int bit = 31; bit >= 0; --bit) {
                    unsigned cand = T | (1u << bit);
                    unsigned bal = __ballot_sync(0xffffffffu, u >= cand);
                    if (__popc(bal) >= STOP) T = cand;
                }
                unsigned gt = __ballot_sync(0xffffffffu, u > T);
                unsigned eq = __ballot_sync(0xffffffffu, u == T);
                int need = STOP - __popc(gt);
                bool take = ((eq >> lane) & 1u) &&
                            (__popc(eq & ((1u << lane) - 1u)) < need);
                unsigned eqt = __ballot_sync(0xffffffffu, take);
                sel = gt | eqt;
            }
            mysel[qi] = sel;
        }
        __syncwarp();
        unsigned wsel0 = mysel[0] | mysel[1] | mysel[2] | mysel[3];
        if (lane == 0) atomicOr(&unionm, wsel0);

        // ---- compressed PV ----
        int j4hi = qb >> 2;
        for (int j4 = 0; j4 <= j4hi; j4++) {
            float4 pb[4];
            #pragma unroll
            for (int qi = 0; qi < 4; qi++)
                pb[qi] = *(const float4*)&p_sh[(w + qi*8)*64 + j4*4];
            #pragma unroll
            for (int jj = 0; jj < 4; jj++) {
                u64 v = vbU[(j4*4 + jj)*32 + lane];
                #pragma unroll
                for (int qi = 0; qi < 4; qi++)
                    accC[qi] = ffma2(dup2(f4c(pb[qi], jj)), v, accC[qi]);
            }
        }
    }
    unsigned wsel = mysel[0] | mysel[1] | mysel[2] | mysel[3];
    __syncthreads();
    unsigned um = unionm;
    if (tid == 0) {
        int c = 0;
        for (int kb = 0; kb <= qb; kb++)
            if ((um >> kb) & 1u) list[c++] = kb;
        lcnt = c;
        list[c] = list[c > 0 ? c - 1 : 0];
    }
    __syncthreads();
    int cnt = lcnt;

    // ================= Phase B: paired selected tiles =================
    for (int it = 0; it < cnt; it += 2) {
        int kb0 = list[it];
        int kb1 = list[it + 1];
        bool valid1 = (it + 1 < cnt);
        for (int i = tid; i < 512; i += 256) {
            int row = i >> 4, c4 = i & 15;
            int g0 = ((b*Nc + kb0*BSc + row)*Hc + h)*Dc;
            int g1 = ((b*Nc + kb1*BSc + row)*Hc + h)*Dc;
            kb4[c4*64 + (row ^ c4)]        = ((const float4*)(pk + g0))[c4];
            kb4[c4*64 + ((row + 32) ^ c4)] = ((const float4*)(pk + g1))[c4];
            vb4[row*16 + c4]        = ((const float4*)(pvv + g0))[c4];
            vb4[(row + 32)*16 + c4] = ((const float4*)(pvv + g1))[c4];
        }
        __syncthreads();

        bool need0 = (wsel >> kb0) & 1u;
        bool need1 = valid1 && ((wsel >> kb1) & 1u);
        if (need0 | need1) {
            u64 s0[4] = {0,0,0,0}, s1[4] = {0,0,0,0};
            #pragma unroll
            for (int d4 = 0; d4 < 16; d4++) {
                ulonglong2 k0 = kbU[d4*64 + (lane ^ d4)];
                ulonglong2 k1 = kbU[d4*64 + ((lane + 32) ^ d4)];
                #pragma unroll
                for (int qi = 0; qi < 4; qi++) {
                    ulonglong2 q = qshU[(w + qi*8)*16 + d4];
                    s0[qi] = ffma2(q.x, k0.x, s0[qi]);
                    s0[qi] = ffma2(q.y, k0.y, s0[qi]);
                    s1[qi] = ffma2(q.x, k1.x, s1[qi]);
                    s1[qi] = ffma2(q.y, k1.y, s1[qi]);
                }
            }
            #pragma unroll
            for (int qi = 0; qi < 4; qi++) {
                int r = w + qi*8;
                int jmax0 = (kb0 == qb) ? r : 31;
                int jmax1 = (kb1 == qb) ? r : 31;
                bool u0 = ((mysel[qi] >> kb0) & 1u) && (lane <= jmax0);
                bool u1 = valid1 && ((mysel[qi] >> kb1) & 1u) && (lane <= jmax1);
                float2 f0 = u2f2(s0[qi]), f1 = u2f2(s1[qi]);
                p_sh[r*64 + lane]      = u0 ? siluf((f0.x + f0.y) * SCALE) : 0.f;
                p_sh[r*64 + 32 + lane] = u1 ? siluf((f1.x + f1.y) * SCALE) : 0.f;
            }
            __syncwarp();
            if (need0) {
                #pragma unroll
                for (int j4 = 0; j4 < 8; j4++) {
                    float4 pb[4];
                    #pragma unroll
                    for (int qi = 0; qi < 4; qi++)
                        pb[qi] = *(const float4*)&p_sh[(w + qi*8)*64 + j4*4];
                    #pragma unroll
                    for (int jj = 0; jj < 4; jj++) {
                        u64 v = vbU[(j4*4 + jj)*32 + lane];
                        #pragma unroll
                        for (int qi = 0; qi < 4; qi++)
                            accS[qi] = ffma2(dup2(f4c(pb[qi], jj)), v, accS[qi]);
                    }
                }
            }
            if (need1) {
                #pragma unroll
                for (int j4 = 8; j4 < 16; j4++) {
                    float4 pb[4];
                    #pragma unroll
                    for (int qi = 0; qi < 4; qi++)
                        pb[qi] = *(const float4*)&p_sh[(w + qi*8)*64 + j4*4];
                    #pragma unroll
                    for (int jj = 0; jj < 4; jj++) {
                        u64 v = vbU[(j4*4 + jj)*32 + lane];
                        #pragma unroll
                        for (int qi = 0; qi < 4; qi++)
                            accS[qi] = ffma2(dup2(f4c(pb[qi], jj)), v, accS[qi]);
                    }
                }
            }
        }
        __syncthreads();
    }

    // ================= Output + gates (epilogue) =================
    const float* qs = (const float*)qsh4;
    const float* gw = gate_w + h*Dc*3;
    #pragma unroll
    for (int qi = 0; qi < 4; qi++) {
        int r = w + qi*8;
        if (r >= nvalid) continue;   // warp-uniform
        float q0 = qs[r*64 + 2*lane], q1 = qs[r*64 + 2*lane + 1];
        float pg0 = q0*gw[(2*lane)*3 + 0] + q1*gw[(2*lane+1)*3 + 0];
        float pg1 = q0*gw[(2*lane)*3 + 1] + q1*gw[(2*lane+1)*3 + 1];
        #pragma unroll
        for (int off = 16; off > 0; off >>= 1) {
            pg0 += __shfl_xor_sync(0xffffffffu, pg0, off);
            pg1 += __shfl_xor_sync(0xffffffffu, pg1, off);
        }
        float gcv = 1.f / (1.f + __expf(-pg0));
        float gsv = 1.f / (1.f + __expf(-pg1));
        float2 c = u2f2(accC[qi]), s2 = u2f2(accS[qi]);
        int n = qb*BSc + r;
        int o = ((t0 + n)*Hc + h)*Dc;
        float2 o2;
        o2.x = c.x*gcv + s2.x*gsv;
        o2.y = c.y*gcv + s2.y*gsv;
        *((float2*)(out + o) + lane) = o2;
    }
}

extern "C" void kernel_launch(void* const* d_in, const int* in_sizes, int n_in,
                              void* d_out, int out_size) {
    const float* pq   = (const float*)d_in[4];
    const float* pk   = (const float*)d_in[5];
    const float* pv   = (const float*)d_in[6];
    const int*   xoff = (const int*)d_in[7];
    const float* gw   = (const float*)d_in[8];
    float* out = (float*)d_out;

    meanKV<<<Bc*NBc*Hc, 64>>>(pk, pv);
    dim3 grid(NBc, Hc, Bc);
    hstu_main<<<grid, 256>>>(pq, pk, pv, gw, xoff, out);
}